// round 1
// baseline (speedup 1.0000x reference)
#include <cuda_runtime.h>
#include <math.h>

#define NN 50000
#define EE 800000
#define DD 128
#define MAXNORM (1.0f - 4e-3f)
#define MIN_NORM 1e-15f

// Scratch (no cudaMalloc allowed)
__device__ float g_deg[NN];
__device__ float g_dis[NN];

// deg[i] = 1 (fresh self-loop weight)
__global__ void k_init_deg() {
    int i = blockIdx.x * blockDim.x + threadIdx.x;
    if (i < NN) g_deg[i] = 1.0f;
}

// deg[r] += 1 for every non-self edge (source row index)
__global__ void k_count(const int* __restrict__ row, const int* __restrict__ col) {
    int e = blockIdx.x * blockDim.x + threadIdx.x;
    if (e < EE) {
        int r = row[e], c = col[e];
        if (r != c) atomicAdd(&g_deg[r], 1.0f);
    }
}

// out[i] = x[i] / deg[i]  (self-loop term, dis[i]^2 = 1/deg[i]); also dis = rsqrt(deg)
__global__ void k_init_out(const float* __restrict__ x, float* __restrict__ out) {
    int t = blockIdx.x * blockDim.x + threadIdx.x;
    const int total = NN * (DD / 4);
    if (t >= total) return;
    int rowi = t >> 5;                // t / (DD/4), DD/4 == 32
    float deg = g_deg[rowi];
    if ((t & 31) == 0) g_dis[rowi] = rsqrtf(deg);
    float inv = 1.0f / deg;
    float4 v = reinterpret_cast<const float4*>(x)[t];
    v.x *= inv; v.y *= inv; v.z *= inv; v.w *= inv;
    reinterpret_cast<float4*>(out)[t] = v;
}

// One warp per edge: out[r*D + lane*4 .. +3] += dis[r]*dis[c] * x[c*D + ...]
__global__ void k_scatter(const int* __restrict__ row, const int* __restrict__ col,
                          const float* __restrict__ x, float* __restrict__ out) {
    int warp = (blockIdx.x * blockDim.x + threadIdx.x) >> 5;
    int lane = threadIdx.x & 31;
    if (warp >= EE) return;
    int r = __ldg(row + warp);
    int c = __ldg(col + warp);
    if (r == c) return;
    float nw = __ldg(g_dis + r) * __ldg(g_dis + c);
    float4 v = __ldg(reinterpret_cast<const float4*>(x + (size_t)c * DD) + lane);
    float a = v.x * nw, b = v.y * nw, cc = v.z * nw, d = v.w * nw;
    float* dst = out + (size_t)r * DD + lane * 4;
    asm volatile("red.global.add.v4.f32 [%0], {%1, %2, %3, %4};"
                 :: "l"(dst), "f"(a), "f"(b), "f"(cc), "f"(d) : "memory");
}

// One warp per row: fused expmap0 + proj as a single scale
__global__ void k_final(float* __restrict__ out) {
    int warp = (blockIdx.x * blockDim.x + threadIdx.x) >> 5;
    int lane = threadIdx.x & 31;
    if (warp >= NN) return;
    float4* p = reinterpret_cast<float4*>(out + (size_t)warp * DD);
    float4 v = p[lane];
    float ss = v.x * v.x + v.y * v.y + v.z * v.z + v.w * v.w;
    #pragma unroll
    for (int o = 16; o; o >>= 1) ss += __shfl_xor_sync(0xffffffffu, ss, o);
    float n  = sqrtf(ss);
    float nh = fmaxf(n, MIN_NORM);
    float t  = tanhf(nh) / nh;          // expmap0 scale
    float pn = n * t;                   // norm after expmap0
    float s  = (pn > MAXNORM) ? (MAXNORM / nh) : t;   // proj composed
    v.x *= s; v.y *= s; v.z *= s; v.w *= s;
    p[lane] = v;
}

extern "C" void kernel_launch(void* const* d_in, const int* in_sizes, int n_in,
                              void* d_out, int out_size) {
    const float* x   = (const float*)d_in[0];
    const int*   ei  = (const int*)d_in[1];
    const int*   row = ei;
    const int*   col = ei + EE;
    float* out = (float*)d_out;

    k_init_deg<<<(NN + 255) / 256, 256>>>();
    k_count<<<(EE + 255) / 256, 256>>>(row, col);
    k_init_out<<<(NN * (DD / 4) + 255) / 256, 256>>>(x, out);
    // 8 warps per block, 1 warp per edge
    k_scatter<<<(EE + 7) / 8, 256>>>(row, col, x, out);
    k_final<<<(NN + 7) / 8, 256>>>(out);
}

// round 2
// speedup vs baseline: 1.8684x; 1.8684x over previous
#include <cuda_runtime.h>
#include <math.h>

#define NN 50000
#define EE 800000
#define DD 128
#define MAXNORM (1.0f - 4e-3f)
#define MIN_NORM 1e-15f

// ---- device scratch (no cudaMalloc allowed) ----
__device__ int   g_cnt[NN];      // per-row non-self edge count
__device__ int   g_off[NN];      // start of row's segment in g_col
__device__ int   g_cur[NN];      // fill cursor
__device__ float g_dis[NN];      // rsqrt(deg), deg = cnt + 1 (self loop)
__device__ int   g_col[EE];      // neighbor cols grouped by destination row
__device__ int   g_total;        // segment allocator

// zero counters (every call: determinism under graph replay)
__global__ void k_zero() {
    int i = blockIdx.x * blockDim.x + threadIdx.x;
    if (i < NN) g_cnt[i] = 0;
    if (i == 0) g_total = 0;
}

// count non-self edges per destination row
__global__ void k_count(const int* __restrict__ row, const int* __restrict__ col) {
    int e = blockIdx.x * blockDim.x + threadIdx.x;
    if (e < EE) {
        int r = row[e];
        if (r != col[e]) atomicAdd(&g_cnt[r], 1);
    }
}

// per-block scan + one global atomic per block -> contiguous (unordered) segments
__global__ void k_offsets() {
    __shared__ int sh[256];
    __shared__ int base;
    int i = blockIdx.x * 256 + threadIdx.x;
    int v = (i < NN) ? g_cnt[i] : 0;
    sh[threadIdx.x] = v;
    __syncthreads();
    #pragma unroll
    for (int o = 1; o < 256; o <<= 1) {
        int t = (threadIdx.x >= o) ? sh[threadIdx.x - o] : 0;
        __syncthreads();
        sh[threadIdx.x] += t;
        __syncthreads();
    }
    if (threadIdx.x == 255) base = atomicAdd(&g_total, sh[255]);
    __syncthreads();
    if (i < NN) {
        int off = base + sh[threadIdx.x] - v;   // exclusive within block + block base
        g_off[i] = off;
        g_cur[i] = off;
        g_dis[i] = rsqrtf((float)(v + 1));
    }
}

// scatter cols into destination-grouped segments
__global__ void k_fill(const int* __restrict__ row, const int* __restrict__ col) {
    int e = blockIdx.x * blockDim.x + threadIdx.x;
    if (e < EE) {
        int r = row[e], c = col[e];
        if (r != c) g_col[atomicAdd(&g_cur[r], 1)] = c;
    }
}

// one warp per output row: register accumulate + fused expmap0/proj epilogue
__global__ void __launch_bounds__(256) k_agg(const float* __restrict__ x,
                                             float* __restrict__ out) {
    int warp = (blockIdx.x * blockDim.x + threadIdx.x) >> 5;
    int lane = threadIdx.x & 31;
    if (warp >= NN) return;

    const float4* x4 = reinterpret_cast<const float4*>(x);
    int off = g_off[warp];
    int cnt = g_cnt[warp];
    float dr = g_dis[warp];

    float4 s = make_float4(0.f, 0.f, 0.f, 0.f);
    int j = off, end = off + cnt;
    // unroll by 4 neighbors for MLP against L2 latency
    for (; j + 4 <= end; j += 4) {
        int c0 = __ldg(g_col + j + 0);
        int c1 = __ldg(g_col + j + 1);
        int c2 = __ldg(g_col + j + 2);
        int c3 = __ldg(g_col + j + 3);
        float w0 = __ldg(g_dis + c0), w1 = __ldg(g_dis + c1);
        float w2 = __ldg(g_dis + c2), w3 = __ldg(g_dis + c3);
        float4 v0 = __ldg(x4 + (size_t)c0 * 32 + lane);
        float4 v1 = __ldg(x4 + (size_t)c1 * 32 + lane);
        float4 v2 = __ldg(x4 + (size_t)c2 * 32 + lane);
        float4 v3 = __ldg(x4 + (size_t)c3 * 32 + lane);
        s.x += w0 * v0.x + w1 * v1.x + w2 * v2.x + w3 * v3.x;
        s.y += w0 * v0.y + w1 * v1.y + w2 * v2.y + w3 * v3.y;
        s.z += w0 * v0.z + w1 * v1.z + w2 * v2.z + w3 * v3.z;
        s.w += w0 * v0.w + w1 * v1.w + w2 * v2.w + w3 * v3.w;
    }
    for (; j < end; j++) {
        int c = __ldg(g_col + j);
        float w = __ldg(g_dis + c);
        float4 v = __ldg(x4 + (size_t)c * 32 + lane);
        s.x += w * v.x; s.y += w * v.y; s.z += w * v.z; s.w += w * v.w;
    }

    // res = dr * sum + (1/deg) * x[r]   (self-loop weight = dr^2)
    float4 xr = __ldg(x4 + (size_t)warp * 32 + lane);
    float selfw = dr * dr;
    float4 r;
    r.x = dr * s.x + selfw * xr.x;
    r.y = dr * s.y + selfw * xr.y;
    r.z = dr * s.z + selfw * xr.z;
    r.w = dr * s.w + selfw * xr.w;

    // fused expmap0 + proj: single per-row scale
    float ss = r.x * r.x + r.y * r.y + r.z * r.z + r.w * r.w;
    #pragma unroll
    for (int o = 16; o; o >>= 1) ss += __shfl_xor_sync(0xffffffffu, ss, o);
    float n  = sqrtf(ss);
    float nh = fmaxf(n, MIN_NORM);
    float t  = tanhf(nh) / nh;
    float sc = (n * t > MAXNORM) ? (MAXNORM / nh) : t;
    r.x *= sc; r.y *= sc; r.z *= sc; r.w *= sc;
    reinterpret_cast<float4*>(out)[(size_t)warp * 32 + lane] = r;
}

extern "C" void kernel_launch(void* const* d_in, const int* in_sizes, int n_in,
                              void* d_out, int out_size) {
    const float* x   = (const float*)d_in[0];
    const int*   ei  = (const int*)d_in[1];
    const int*   row = ei;
    const int*   col = ei + EE;
    float* out = (float*)d_out;

    k_zero   <<<(NN + 255) / 256, 256>>>();
    k_count  <<<(EE + 255) / 256, 256>>>(row, col);
    k_offsets<<<(NN + 255) / 256, 256>>>();
    k_fill   <<<(EE + 255) / 256, 256>>>(row, col);
    k_agg    <<<(NN + 7) / 8, 256>>>(x, out);   // 8 warps/block, 1 warp/row
}